// round 12
// baseline (speedup 1.0000x reference)
#include <cuda_runtime.h>
#include <cuda_fp16.h>
#include <cstdint>

#define NSUP 131072
#define DD   512
#define CC   1024
#define LL   3
#define MTILE 64
#define NCH  8          // K chunks of 64

// ---------------- device scratch ----------------
__device__ __half g_Bh[(size_t)LL * DD * DD];   // W1^T fp16: [l][n][k]
__device__ int   g_perm[NSUP];
__device__ int   g_cls[NSUP];
__device__ int   g_counts[CC];
__device__ int   g_cursor[CC];
__device__ int   g_off[CC];
__device__ float g_S[LL * CC * DD];

// ---------------- helpers ----------------
__device__ __forceinline__ uint32_t smem_u32(const void* p) {
    uint32_t a;
    asm("{ .reg .u64 t; cvta.to.shared.u64 t, %1; cvt.u32.u64 %0, t; }" : "=r"(a) : "l"(p));
    return a;
}
__device__ __forceinline__ uint32_t f2_to_h2(float lo, float hi) {
    uint32_t r;
    asm("cvt.rn.f16x2.f32 %0, %1, %2;" : "=r"(r) : "f"(hi), "f"(lo));
    return r;
}
__device__ __forceinline__ void cp_async16(void* sdst, const void* gsrc) {
    unsigned s = (unsigned)__cvta_generic_to_shared(sdst);
    asm volatile("cp.async.cg.shared.global [%0], [%1], 16;" :: "r"(s), "l"(gsrc));
}
__device__ __forceinline__ void cp_commit() { asm volatile("cp.async.commit_group;"); }
__device__ __forceinline__ void cp_wait0()  { asm volatile("cp.async.wait_group 0;"); }

__device__ __forceinline__ void ldsm4(uint32_t* r, uint32_t addr) {
    asm volatile("ldmatrix.sync.aligned.m8n8.x4.shared.b16 {%0,%1,%2,%3}, [%4];"
                 : "=r"(r[0]), "=r"(r[1]), "=r"(r[2]), "=r"(r[3]) : "r"(addr));
}
__device__ __forceinline__ void mma16816(float* c, const uint32_t* a, uint32_t b0, uint32_t b1) {
    asm volatile(
        "mma.sync.aligned.m16n8k16.row.col.f32.f16.f16.f32 "
        "{%0,%1,%2,%3}, {%4,%5,%6,%7}, {%8,%9}, {%0,%1,%2,%3};"
        : "+f"(c[0]), "+f"(c[1]), "+f"(c[2]), "+f"(c[3])
        : "r"(a[0]), "r"(a[1]), "r"(a[2]), "r"(a[3]), "r"(b0), "r"(b1));
}

// ---------------- small kernels ----------------
__global__ void zero_kernel() {
    int i = blockIdx.x * 256 + threadIdx.x;
    if (i < LL * CC * DD) g_S[i] = 0.f;
    if (i < CC) { g_counts[i] = 0; g_cursor[i] = 0; }
}
__global__ void hist_kernel(const int* __restrict__ labels) {
    int i = blockIdx.x * 256 + threadIdx.x;
    if (i < NSUP) atomicAdd(&g_counts[labels[i]], 1);
}
__global__ void scan_kernel() {
    __shared__ int tmp[CC];
    int t = threadIdx.x;
    int v = g_counts[t];
    tmp[t] = v;
    __syncthreads();
    for (int o = 1; o < CC; o <<= 1) {
        int add = (t >= o) ? tmp[t - o] : 0;
        __syncthreads();
        tmp[t] += add;
        __syncthreads();
    }
    g_off[t] = tmp[t] - v;
}
__global__ void perm_kernel(const int* __restrict__ labels) {
    int i = blockIdx.x * 256 + threadIdx.x;
    if (i >= NSUP) return;
    int c = labels[i];
    int pos = g_off[c] + atomicAdd(&g_cursor[c], 1);
    g_perm[pos] = i;
    g_cls[pos] = c;
}
__global__ void bprep_kernel(const float* __restrict__ W1) {
    int idx = blockIdx.x * 256 + threadIdx.x;
    if (idx >= LL * DD * DD) return;
    int l = idx >> 18;
    int rem = idx & ((1 << 18) - 1);
    int k = rem >> 9, n = rem & 511;
    g_Bh[((size_t)(l * DD + n) << 9) + k] = __float2half_rn(W1[idx]);
}

// ---------------- fused level kernel: 1 CTA = 64 rows x all 3 levels ----------------
// smem: A resident 64KB | B 2x64KB (H fp16 overlays B stage 1)
//       | b1[3][512] | gamma[3][512] | beta[3][512] | cls | perm | part_s | part_q | mu | rstd
#define OFF_A   0
#define OFF_B   65536
#define OFF_B1  196608
#define OFF_G   202752
#define OFF_BT  208896
#define OFF_CL  215040
#define OFF_PM  215296
#define OFF_PS  215552
#define OFF_PQ  217600
#define OFF_MU  219648
#define OFF_RS  219904
#define LVL_SMEM_BYTES (220160 + 1024)

// B chunk loader: 4096 x 16B over 256 threads (commits its own group)
__device__ __forceinline__ void load_B(char* Bd, const __half* Bp, int ch, int tid) {
#pragma unroll
    for (int i = 0; i < 16; i++) {
        int o = tid + 256 * i;
        int n = o >> 3, b = (o & 7) * 16;
        uint32_t sw = (uint32_t)(n * 128) + (uint32_t)(b ^ ((n & 7) << 4));
        cp_async16(Bd + sw, (const char*)Bp + ((size_t)n * 1024 + ch * 128 + b));
    }
    cp_commit();
}

__global__ __launch_bounds__(256, 1)
void level_kernel(const float* __restrict__ X, const float* __restrict__ b1,
                  const float* __restrict__ gamma, const float* __restrict__ beta)
{
    extern __shared__ char raw[];
    char* sm = (char*)(((uintptr_t)raw + 1023) & ~(uintptr_t)1023);
    const int row0 = blockIdx.x * MTILE;
    const int tid = threadIdx.x;
    const int wid = tid >> 5, lane = tid & 31;   // 8 warps, warp tile 64 rows x 64 cols
    const uint32_t sbase = smem_u32(sm);

    float* b1s = (float*)(sm + OFF_B1);   // [3][512]
    float* gms = (float*)(sm + OFF_G);
    float* bts = (float*)(sm + OFF_BT);
    int*   clss = (int*)(sm + OFF_CL);
    int*   sperm = (int*)(sm + OFF_PM);
    float* part_s = (float*)(sm + OFF_PS);   // [64][8]
    float* part_q = (float*)(sm + OFF_PQ);
    float* smu = (float*)(sm + OFF_MU);
    float* srs = (float*)(sm + OFF_RS);

    // preload ALL levels' params once
#pragma unroll
    for (int i = 0; i < 6; i++) {
        int o = tid + 256 * i;               // 0..1535 = LL*DD
        b1s[o] = b1[o];
        gms[o] = gamma[o];
        bts[o] = beta[o];
    }
    if (tid < MTILE) {
        clss[tid] = g_cls[row0 + tid];
        sperm[tid] = g_perm[row0 + tid];
    }
    __syncthreads();

    // start B level-0 chunk-0 immediately (overlaps A gather)
    load_B(sm + OFF_B, g_Bh, 0, tid);

    // A gather full-K once: f32 -> fp16, swizzled chunked layout
#pragma unroll
    for (int ch = 0; ch < NCH; ch++) {
#pragma unroll
        for (int i = 0; i < 2; i++) {
            int o = tid + 256 * i;
            int r = o >> 3, b = (o & 7) * 16;
            const float* src = X + (size_t)sperm[r] * DD + ch * 64 + (o & 7) * 8;
            float4 x0 = *(const float4*)(src);
            float4 x1 = *(const float4*)(src + 4);
            uint4 v;
            v.x = f2_to_h2(x0.x, x0.y);
            v.y = f2_to_h2(x0.z, x0.w);
            v.z = f2_to_h2(x1.x, x1.y);
            v.w = f2_to_h2(x1.z, x1.w);
            uint32_t sw = (uint32_t)(r * 128) + (uint32_t)(b ^ ((r & 7) << 4));
            *(uint4*)(sm + OFF_A + ch * 8192 + sw) = v;
        }
    }

    // fragment address components (validated R5/R6/R9/R11)
    uint32_t art[4], axr[4];
#pragma unroll
    for (int mf = 0; mf < 4; mf++) {
        int r = (lane & 15) + mf * 16;
        art[mf] = (uint32_t)(r * 128);
        axr[mf] = (uint32_t)((r & 7) << 4);
    }
    const uint32_t a_ts = (uint32_t)((lane >> 4) * 16);
    int bn = (lane & 7) + ((lane >> 4) & 1) * 8;
    const uint32_t b_kh = (uint32_t)(((lane >> 3) & 1) * 16);
    uint32_t brt[4], bxr[4];
#pragma unroll
    for (int nf2 = 0; nf2 < 4; nf2++) {
        int n = wid * 64 + nf2 * 16 + bn;
        brt[nf2] = (uint32_t)(n * 128);
        bxr[nf2] = (uint32_t)((n & 7) << 4);
    }

    float acc[4][8][4];
#pragma unroll
    for (int i = 0; i < 4; i++)
#pragma unroll
        for (int j = 0; j < 8; j++)
#pragma unroll
            for (int q = 0; q < 4; q++) acc[i][j][q] = 0.f;

    __half* Hh = (__half*)(sm + OFF_B + 65536);   // overlays B stage 1

    for (int l = 0; l < LL; l++) {
        for (int ch = 0; ch < NCH; ch++) {
            const int buf = ch & 1;
            cp_wait0();
            __syncthreads();   // buf ready + all threads past previous compute/epilogue

            // prefetch next chunk (possibly next level's ch0) into other stage
            int nl = l, nc = ch + 1;
            if (nc == NCH) { nl = l + 1; nc = 0; }
            if (nl < LL)
                load_B(sm + OFF_B + (buf ^ 1) * 65536,
                       g_Bh + (size_t)nl * DD * DD, nc, tid);

            const uint32_t Ab = sbase + OFF_A + ch * 8192;
            const uint32_t Bb = sbase + OFF_B + buf * 65536;
#pragma unroll
            for (int ks = 0; ks < 4; ks++) {
                const uint32_t koff = ks * 32;
                uint32_t a[4][4];
#pragma unroll
                for (int mf = 0; mf < 4; mf++)
                    ldsm4(a[mf], Ab + art[mf] + ((koff + a_ts) ^ axr[mf]));
#pragma unroll
                for (int nf2 = 0; nf2 < 4; nf2++) {
                    uint32_t bh[4];
                    ldsm4(bh, Bb + brt[nf2] + ((koff + b_kh) ^ bxr[nf2]));
#pragma unroll
                    for (int mf = 0; mf < 4; mf++) {
                        mma16816(acc[mf][nf2 * 2],     a[mf], bh[0], bh[1]);
                        mma16816(acc[mf][nf2 * 2 + 1], a[mf], bh[2], bh[3]);
                    }
                }
            }
        }

        // ================= epilogue for level l ===================================
        const float* b1l = b1s + l * DD;
        const float* gml = gms + l * DD;
        const float* btl = bts + l * DD;

        // fold b1 into acc, per-thread partial sums per row-position
        float s8[4][2], q8[4][2];
#pragma unroll
        for (int mf = 0; mf < 4; mf++) { s8[mf][0] = s8[mf][1] = 0.f; q8[mf][0] = q8[mf][1] = 0.f; }
#pragma unroll
        for (int nf = 0; nf < 8; nf++) {
            const int colb = wid * 64 + (lane & 3) * 2 + nf * 8;
            const float bb0 = b1l[colb], bb1 = b1l[colb + 1];
#pragma unroll
            for (int mf = 0; mf < 4; mf++) {
#pragma unroll
                for (int hh = 0; hh < 2; hh++) {
                    float v0 = acc[mf][nf][2 * hh]     + bb0;
                    float v1 = acc[mf][nf][2 * hh + 1] + bb1;
                    acc[mf][nf][2 * hh]     = v0;
                    acc[mf][nf][2 * hh + 1] = v1;
                    s8[mf][hh] += v0 + v1;
                    q8[mf][hh] += v0 * v0 + v1 * v1;
                }
            }
        }
        // combine the 4 lanes sharing each row, store warp partials
#pragma unroll
        for (int mf = 0; mf < 4; mf++)
#pragma unroll
            for (int hh = 0; hh < 2; hh++) {
                float s = s8[mf][hh], q = q8[mf][hh];
                s += __shfl_xor_sync(0xffffffffu, s, 1);
                s += __shfl_xor_sync(0xffffffffu, s, 2);
                q += __shfl_xor_sync(0xffffffffu, q, 1);
                q += __shfl_xor_sync(0xffffffffu, q, 2);
                if ((lane & 3) == 0) {
                    int row = (lane >> 2) + 8 * hh + 16 * mf;
                    part_s[row * 8 + wid] = s;
                    part_q[row * 8 + wid] = q;
                }
            }
        __syncthreads();
        if (tid < MTILE) {
            float s = 0.f, q = 0.f;
#pragma unroll
            for (int w = 0; w < 8; w++) { s += part_s[tid * 8 + w]; q += part_q[tid * 8 + w]; }
            float mu = s * (1.f / 512.f);
            float var = q * (1.f / 512.f) - mu * mu;
            smu[tid] = mu;
            srs[tid] = rsqrtf(var + 1e-5f);
        }
        __syncthreads();

        // normalize + ReLU from registers -> fp16 H
#pragma unroll
        for (int nf = 0; nf < 8; nf++) {
            const int colb = wid * 64 + (lane & 3) * 2 + nf * 8;
            const float g0 = gml[colb], g1 = gml[colb + 1];
            const float t0 = btl[colb], t1 = btl[colb + 1];
#pragma unroll
            for (int mf = 0; mf < 4; mf++)
#pragma unroll
                for (int hh = 0; hh < 2; hh++) {
                    int row = (lane >> 2) + 8 * hh + 16 * mf;
                    float mu = smu[row], rs = srs[row];
                    float v0 = fmaxf((acc[mf][nf][2 * hh]     - mu) * rs * g0 + t0, 0.f);
                    float v1 = fmaxf((acc[mf][nf][2 * hh + 1] - mu) * rs * g1 + t1, 0.f);
                    *(uint32_t*)&Hh[row * 512 + colb] = f2_to_h2(v0, v1);
                }
        }
        __syncthreads();

        // class-segment reduce (2 cols/thread) + atomics
        {
            float* Sl = g_S + (size_t)l * CC * DD;
            const int c0 = 2 * tid;
            float s0 = 0.f, s1 = 0.f;
            int cur = clss[0];
#pragma unroll 4
            for (int r = 0; r < MTILE; r++) {
                int c2 = clss[r];
                if (c2 != cur) {
                    atomicAdd(&Sl[(size_t)cur * DD + c0], s0);
                    atomicAdd(&Sl[(size_t)cur * DD + c0 + 1], s1);
                    s0 = 0.f; s1 = 0.f; cur = c2;
                }
                __half2 hv = *(__half2*)&Hh[r * 512 + c0];
                float2 f = __half22float2(hv);
                s0 += f.x; s1 += f.y;
            }
            atomicAdd(&Sl[(size_t)cur * DD + c0], s0);
            atomicAdd(&Sl[(size_t)cur * DD + c0 + 1], s1);
        }

        // reset accumulators for next level
#pragma unroll
        for (int i = 0; i < 4; i++)
#pragma unroll
            for (int j = 0; j < 8; j++)
#pragma unroll
                for (int q = 0; q < 4; q++) acc[i][j][q] = 0.f;
        // next level's top-of-loop sync orders Hh reads vs its ch1 load into stage 1
    }
}

// ---------------- finalize: 8 classes per CTA (grid 128) ----------------
#define FIN_SMEM_BYTES ((256 + 16384) * 4)

__global__ __launch_bounds__(512, 1)
void finalize_kernel(const float* __restrict__ W2, const float* __restrict__ b2,
                     const float* __restrict__ temps, float* __restrict__ out)
{
    extern __shared__ float smf[];
    float* As = smf;          // [8][32]
    float* Bs = smf + 256;    // [32][512]
    const int tid = threadIdx.x;
    const int row0 = blockIdx.x * 8;
    const int c_t = tid & 63, r_t = tid >> 6;   // r_t = class index 0..7

    float t0 = temps[0], t1 = temps[1], t2 = temps[2];
    float mx = fmaxf(t0, fmaxf(t1, t2));
    float e0 = expf(t0 - mx), e1 = expf(t1 - mx), e2 = expf(t2 - mx);
    float inv = 1.f / (e0 + e1 + e2);
    float w[3] = {e0 * inv, e1 * inv, e2 * inv};

    float acc[8];
#pragma unroll
    for (int j = 0; j < 8; j++) acc[j] = 0.f;

    const int c0 = c_t << 2;
    for (int l = 0; l < LL; l++) {
        for (int ch = 0; ch < 16; ch++) {
            __syncthreads();
            if (tid < 256) {
                int row = tid >> 5, kk = tid & 31;
                int cl = row0 + row;
                float cnt = fmaxf((float)g_counts[cl], 1.f);
                As[row * 32 + kk] =
                    g_S[(size_t)l * CC * DD + (size_t)cl * DD + ch * 32 + kk] * (w[l] / cnt);
            }
#pragma unroll
            for (int i = 0; i < 8; i++) {
                int idx = tid + i * 512;
                int k = idx >> 7, c4 = (idx & 127) << 2;
                *(float4*)(Bs + k * 512 + c4) =
                    *(const float4*)(W2 + (size_t)l * DD * DD + (size_t)(ch * 32 + k) * DD + c4);
            }
            __syncthreads();
#pragma unroll 4
            for (int k = 0; k < 32; k++) {
                float4 bA = *(const float4*)(Bs + k * 512 + c0);
                float4 bB = *(const float4*)(Bs + k * 512 + 256 + c0);
                float a = As[r_t * 32 + k];
                acc[0] += a * bA.x; acc[1] += a * bA.y;
                acc[2] += a * bA.z; acc[3] += a * bA.w;
                acc[4] += a * bB.x; acc[5] += a * bB.y;
                acc[6] += a * bB.z; acc[7] += a * bB.w;
            }
        }
    }

    {
        int cl = row0 + r_t;
        float has = (g_counts[cl] > 0) ? 1.f : 0.f;
        float4 v0, v1;
        v0.x = acc[0] + has * (w[0] * b2[c0]     + w[1] * b2[DD + c0]     + w[2] * b2[2 * DD + c0]);
        v0.y = acc[1] + has * (w[0] * b2[c0 + 1] + w[1] * b2[DD + c0 + 1] + w[2] * b2[2 * DD + c0 + 1]);
        v0.z = acc[2] + has * (w[0] * b2[c0 + 2] + w[1] * b2[DD + c0 + 2] + w[2] * b2[2 * DD + c0 + 2]);
        v0.w = acc[3] + has * (w[0] * b2[c0 + 3] + w[1] * b2[DD + c0 + 3] + w[2] * b2[2 * DD + c0 + 3]);
        int c1 = 256 + c0;
        v1.x = acc[4] + has * (w[0] * b2[c1]     + w[1] * b2[DD + c1]     + w[2] * b2[2 * DD + c1]);
        v1.y = acc[5] + has * (w[0] * b2[c1 + 1] + w[1] * b2[DD + c1 + 1] + w[2] * b2[2 * DD + c1 + 1]);
        v1.z = acc[6] + has * (w[0] * b2[c1 + 2] + w[1] * b2[DD + c1 + 2] + w[2] * b2[2 * DD + c1 + 2]);
        v1.w = acc[7] + has * (w[0] * b2[c1 + 3] + w[1] * b2[DD + c1 + 3] + w[2] * b2[2 * DD + c1 + 3]);
        *(float4*)(out + (size_t)cl * DD + c0) = v0;
        *(float4*)(out + (size_t)cl * DD + c1) = v1;
    }
}

// ---------------- launch ----------------
extern "C" void kernel_launch(void* const* d_in, const int* in_sizes, int n_in,
                              void* d_out, int out_size)
{
    const float* X      = (const float*)d_in[0];
    const int*   labels = (const int*)d_in[1];
    const float* W1     = (const float*)d_in[2];
    const float* b1     = (const float*)d_in[3];
    const float* gamma  = (const float*)d_in[4];
    const float* beta   = (const float*)d_in[5];
    const float* W2     = (const float*)d_in[6];
    const float* b2     = (const float*)d_in[7];
    const float* temps  = (const float*)d_in[8];
    float* out = (float*)d_out;

    cudaFuncSetAttribute(level_kernel, cudaFuncAttributeMaxDynamicSharedMemorySize,
                         LVL_SMEM_BYTES);
    cudaFuncSetAttribute(finalize_kernel, cudaFuncAttributeMaxDynamicSharedMemorySize,
                         FIN_SMEM_BYTES);

    zero_kernel<<<(LL * CC * DD + 255) / 256, 256>>>();
    hist_kernel<<<(NSUP + 255) / 256, 256>>>(labels);
    scan_kernel<<<1, CC>>>();
    perm_kernel<<<(NSUP + 255) / 256, 256>>>(labels);
    bprep_kernel<<<(LL * DD * DD + 255) / 256, 256>>>(W1);
    level_kernel<<<NSUP / MTILE, 256, LVL_SMEM_BYTES>>>(X, b1, gamma, beta);
    finalize_kernel<<<CC / 8, 512, FIN_SMEM_BYTES>>>(W2, b2, temps, out);
}

// round 13
// speedup vs baseline: 1.4950x; 1.4950x over previous
#include <cuda_runtime.h>
#include <cuda_fp16.h>
#include <cstdint>

#define NSUP 131072
#define DD   512
#define CC   1024
#define LL   3
#define MTILE 64
#define NCH  8          // K chunks of 64

// ---------------- device scratch ----------------
__device__ __half g_Bh[(size_t)LL * DD * DD];   // W1^T fp16: [l][n][k]
__device__ int   g_perm[NSUP];
__device__ int   g_cls[NSUP];
__device__ int   g_counts[CC];
__device__ int   g_cursor[CC];
__device__ int   g_off[CC];
__device__ float g_S[LL * CC * DD];

// ---------------- helpers ----------------
__device__ __forceinline__ uint32_t smem_u32(const void* p) {
    uint32_t a;
    asm("{ .reg .u64 t; cvta.to.shared.u64 t, %1; cvt.u32.u64 %0, t; }" : "=r"(a) : "l"(p));
    return a;
}
__device__ __forceinline__ uint32_t f2_to_h2(float lo, float hi) {
    uint32_t r;
    asm("cvt.rn.f16x2.f32 %0, %1, %2;" : "=r"(r) : "f"(hi), "f"(lo));
    return r;
}
__device__ __forceinline__ void cp_async16(void* sdst, const void* gsrc) {
    unsigned s = (unsigned)__cvta_generic_to_shared(sdst);
    asm volatile("cp.async.cg.shared.global [%0], [%1], 16;" :: "r"(s), "l"(gsrc));
}
__device__ __forceinline__ void cp_commit() { asm volatile("cp.async.commit_group;"); }
__device__ __forceinline__ void cp_wait0()  { asm volatile("cp.async.wait_group 0;"); }

__device__ __forceinline__ void ldsm4(uint32_t* r, uint32_t addr) {
    asm volatile("ldmatrix.sync.aligned.m8n8.x4.shared.b16 {%0,%1,%2,%3}, [%4];"
                 : "=r"(r[0]), "=r"(r[1]), "=r"(r[2]), "=r"(r[3]) : "r"(addr));
}
__device__ __forceinline__ void mma16816(float* c, const uint32_t* a, uint32_t b0, uint32_t b1) {
    asm volatile(
        "mma.sync.aligned.m16n8k16.row.col.f32.f16.f16.f32 "
        "{%0,%1,%2,%3}, {%4,%5,%6,%7}, {%8,%9}, {%0,%1,%2,%3};"
        : "+f"(c[0]), "+f"(c[1]), "+f"(c[2]), "+f"(c[3])
        : "r"(a[0]), "r"(a[1]), "r"(a[2]), "r"(a[3]), "r"(b0), "r"(b1));
}

// ---------------- small kernels ----------------
__global__ void zero_kernel() {
    int i = blockIdx.x * 256 + threadIdx.x;
    if (i < LL * CC * DD) g_S[i] = 0.f;
    if (i < CC) { g_counts[i] = 0; g_cursor[i] = 0; }
}
__global__ void hist_kernel(const int* __restrict__ labels) {
    int i = blockIdx.x * 256 + threadIdx.x;
    if (i < NSUP) atomicAdd(&g_counts[labels[i]], 1);
}
__global__ void scan_kernel() {
    __shared__ int tmp[CC];
    int t = threadIdx.x;
    int v = g_counts[t];
    tmp[t] = v;
    __syncthreads();
    for (int o = 1; o < CC; o <<= 1) {
        int add = (t >= o) ? tmp[t - o] : 0;
        __syncthreads();
        tmp[t] += add;
        __syncthreads();
    }
    g_off[t] = tmp[t] - v;
}
__global__ void perm_kernel(const int* __restrict__ labels) {
    int i = blockIdx.x * 256 + threadIdx.x;
    if (i >= NSUP) return;
    int c = labels[i];
    int pos = g_off[c] + atomicAdd(&g_cursor[c], 1);
    g_perm[pos] = i;
    g_cls[pos] = c;
}
__global__ void bprep_kernel(const float* __restrict__ W1) {
    int idx = blockIdx.x * 256 + threadIdx.x;
    if (idx >= LL * DD * DD) return;
    int l = idx >> 18;
    int rem = idx & ((1 << 18) - 1);
    int k = rem >> 9, n = rem & 511;
    g_Bh[((size_t)(l * DD + n) << 9) + k] = __float2half_rn(W1[idx]);
}

// ---------------- fused level kernel: 1 CTA = 64 rows x all 3 levels (R11 exact) ----
// smem: A resident 8 chunks x 8KB = 64KB | B 2 x 64KB (H fp16 overlays B stage 1)
//       | b1 | gamma | beta | cls | perm | part_s | part_q | mu | rstd
#define OFF_A   0
#define OFF_B   65536
#define OFF_B1  196608
#define OFF_G   198656
#define OFF_BT  200704
#define OFF_CL  202752
#define OFF_PM  203008
#define OFF_PS  203264
#define OFF_PQ  205312
#define OFF_MU  207360
#define OFF_RS  207616
#define LVL_SMEM_BYTES (207872 + 1024)

// B chunk loader: 4096 x 16B over 256 threads (commits its own group)
__device__ __forceinline__ void load_B(char* Bd, const __half* Bp, int ch, int tid) {
#pragma unroll
    for (int i = 0; i < 16; i++) {
        int o = tid + 256 * i;
        int n = o >> 3, b = (o & 7) * 16;
        uint32_t sw = (uint32_t)(n * 128) + (uint32_t)(b ^ ((n & 7) << 4));
        cp_async16(Bd + sw, (const char*)Bp + ((size_t)n * 1024 + ch * 128 + b));
    }
    cp_commit();
}

__global__ __launch_bounds__(256, 1)
void level_kernel(const float* __restrict__ X, const float* __restrict__ b1,
                  const float* __restrict__ gamma, const float* __restrict__ beta)
{
    extern __shared__ char raw[];
    char* sm = (char*)(((uintptr_t)raw + 1023) & ~(uintptr_t)1023);
    const int row0 = blockIdx.x * MTILE;
    const int tid = threadIdx.x;
    const int wid = tid >> 5, lane = tid & 31;   // 8 warps, warp tile 64 rows x 64 cols
    const uint32_t sbase = smem_u32(sm);

    float* b1s = (float*)(sm + OFF_B1);
    float* gms = (float*)(sm + OFF_G);
    float* bts = (float*)(sm + OFF_BT);
    int*   clss = (int*)(sm + OFF_CL);
    int*   sperm = (int*)(sm + OFF_PM);
    float* part_s = (float*)(sm + OFF_PS);   // [64][8]
    float* part_q = (float*)(sm + OFF_PQ);
    float* smu = (float*)(sm + OFF_MU);
    float* srs = (float*)(sm + OFF_RS);

    if (tid < MTILE) {
        clss[tid] = g_cls[row0 + tid];
        sperm[tid] = g_perm[row0 + tid];
    }
    __syncthreads();

    // start B level-0 chunk-0 immediately (overlaps A gather)
    load_B(sm + OFF_B, g_Bh, 0, tid);

    // A gather full-K once: f32 -> fp16, swizzled chunked layout
#pragma unroll
    for (int ch = 0; ch < NCH; ch++) {
#pragma unroll
        for (int i = 0; i < 2; i++) {
            int o = tid + 256 * i;
            int r = o >> 3, b = (o & 7) * 16;
            const float* src = X + (size_t)sperm[r] * DD + ch * 64 + (o & 7) * 8;
            float4 x0 = *(const float4*)(src);
            float4 x1 = *(const float4*)(src + 4);
            uint4 v;
            v.x = f2_to_h2(x0.x, x0.y);
            v.y = f2_to_h2(x0.z, x0.w);
            v.z = f2_to_h2(x1.x, x1.y);
            v.w = f2_to_h2(x1.z, x1.w);
            uint32_t sw = (uint32_t)(r * 128) + (uint32_t)(b ^ ((r & 7) << 4));
            *(uint4*)(sm + OFF_A + ch * 8192 + sw) = v;
        }
    }

    // fragment address components (validated R5/R6/R9/R11)
    uint32_t art[4], axr[4];
#pragma unroll
    for (int mf = 0; mf < 4; mf++) {
        int r = (lane & 15) + mf * 16;
        art[mf] = (uint32_t)(r * 128);
        axr[mf] = (uint32_t)((r & 7) << 4);
    }
    const uint32_t a_ts = (uint32_t)((lane >> 4) * 16);
    int bn = (lane & 7) + ((lane >> 4) & 1) * 8;
    const uint32_t b_kh = (uint32_t)(((lane >> 3) & 1) * 16);
    uint32_t brt[4], bxr[4];
#pragma unroll
    for (int nf2 = 0; nf2 < 4; nf2++) {
        int n = wid * 64 + nf2 * 16 + bn;
        brt[nf2] = (uint32_t)(n * 128);
        bxr[nf2] = (uint32_t)((n & 7) << 4);
    }

    float acc[4][8][4];
#pragma unroll
    for (int i = 0; i < 4; i++)
#pragma unroll
        for (int j = 0; j < 8; j++)
#pragma unroll
            for (int q = 0; q < 4; q++) acc[i][j][q] = 0.f;

    __half* Hh = (__half*)(sm + OFF_B + 65536);   // overlays B stage 1

    for (int l = 0; l < LL; l++) {
        for (int ch = 0; ch < NCH; ch++) {
            const int buf = ch & 1;
            cp_wait0();
            __syncthreads();   // buf ready + all threads past previous compute/epilogue

            // prefetch next chunk (possibly next level's ch0) into other stage
            int nl = l, nc = ch + 1;
            if (nc == NCH) { nl = l + 1; nc = 0; }
            if (nl < LL)
                load_B(sm + OFF_B + (buf ^ 1) * 65536,
                       g_Bh + (size_t)nl * DD * DD, nc, tid);

            const uint32_t Ab = sbase + OFF_A + ch * 8192;
            const uint32_t Bb = sbase + OFF_B + buf * 65536;
#pragma unroll
            for (int ks = 0; ks < 4; ks++) {
                const uint32_t koff = ks * 32;
                uint32_t a[4][4];
#pragma unroll
                for (int mf = 0; mf < 4; mf++)
                    ldsm4(a[mf], Ab + art[mf] + ((koff + a_ts) ^ axr[mf]));
#pragma unroll
                for (int nf2 = 0; nf2 < 4; nf2++) {
                    uint32_t bh[4];
                    ldsm4(bh, Bb + brt[nf2] + ((koff + b_kh) ^ bxr[nf2]));
#pragma unroll
                    for (int mf = 0; mf < 4; mf++) {
                        mma16816(acc[mf][nf2 * 2],     a[mf], bh[0], bh[1]);
                        mma16816(acc[mf][nf2 * 2 + 1], a[mf], bh[2], bh[3]);
                    }
                }
            }
        }

        // ================= epilogue for level l (H never stored pre-norm) ===========
        // params for this level
        __syncthreads();   // everyone done with MMA reads of B stage 0 (H is on stage 1;
                           // next-level ch0 already prefetched into stage 0)
        b1s[tid] = b1[l * DD + tid];       b1s[tid + 256] = b1[l * DD + tid + 256];
        gms[tid] = gamma[l * DD + tid];    gms[tid + 256] = gamma[l * DD + tid + 256];
        bts[tid] = beta[l * DD + tid];     bts[tid + 256] = beta[l * DD + tid + 256];
        __syncthreads();

        // fold b1 into acc, per-thread partial sums per row-position
        float s8[4][2], q8[4][2];
#pragma unroll
        for (int mf = 0; mf < 4; mf++) { s8[mf][0] = s8[mf][1] = 0.f; q8[mf][0] = q8[mf][1] = 0.f; }
#pragma unroll
        for (int nf = 0; nf < 8; nf++) {
            const int colb = wid * 64 + (lane & 3) * 2 + nf * 8;
            const float bb0 = b1s[colb], bb1 = b1s[colb + 1];
#pragma unroll
            for (int mf = 0; mf < 4; mf++) {
#pragma unroll
                for (int hh = 0; hh < 2; hh++) {
                    float v0 = acc[mf][nf][2 * hh]     + bb0;
                    float v1 = acc[mf][nf][2 * hh + 1] + bb1;
                    acc[mf][nf][2 * hh]     = v0;
                    acc[mf][nf][2 * hh + 1] = v1;
                    s8[mf][hh] += v0 + v1;
                    q8[mf][hh] += v0 * v0 + v1 * v1;
                }
            }
        }
        // combine the 4 lanes sharing each row, store warp partials
#pragma unroll
        for (int mf = 0; mf < 4; mf++)
#pragma unroll
            for (int hh = 0; hh < 2; hh++) {
                float s = s8[mf][hh], q = q8[mf][hh];
                s += __shfl_xor_sync(0xffffffffu, s, 1);
                s += __shfl_xor_sync(0xffffffffu, s, 2);
                q += __shfl_xor_sync(0xffffffffu, q, 1);
                q += __shfl_xor_sync(0xffffffffu, q, 2);
                if ((lane & 3) == 0) {
                    int row = (lane >> 2) + 8 * hh + 16 * mf;
                    part_s[row * 8 + wid] = s;
                    part_q[row * 8 + wid] = q;
                }
            }
        __syncthreads();
        if (tid < MTILE) {
            float s = 0.f, q = 0.f;
#pragma unroll
            for (int w = 0; w < 8; w++) { s += part_s[tid * 8 + w]; q += part_q[tid * 8 + w]; }
            float mu = s * (1.f / 512.f);
            float var = q * (1.f / 512.f) - mu * mu;
            smu[tid] = mu;
            srs[tid] = rsqrtf(var + 1e-5f);
        }
        __syncthreads();

        // normalize + ReLU from registers -> fp16 H
#pragma unroll
        for (int nf = 0; nf < 8; nf++) {
            const int colb = wid * 64 + (lane & 3) * 2 + nf * 8;
            const float g0 = gms[colb], g1 = gms[colb + 1];
            const float t0 = bts[colb], t1 = bts[colb + 1];
#pragma unroll
            for (int mf = 0; mf < 4; mf++)
#pragma unroll
                for (int hh = 0; hh < 2; hh++) {
                    int row = (lane >> 2) + 8 * hh + 16 * mf;
                    float mu = smu[row], rs = srs[row];
                    float v0 = fmaxf((acc[mf][nf][2 * hh]     - mu) * rs * g0 + t0, 0.f);
                    float v1 = fmaxf((acc[mf][nf][2 * hh + 1] - mu) * rs * g1 + t1, 0.f);
                    *(uint32_t*)&Hh[row * 512 + colb] = f2_to_h2(v0, v1);
                }
        }
        __syncthreads();

        // class-segment reduce (2 cols/thread) + atomics
        {
            float* Sl = g_S + (size_t)l * CC * DD;
            const int c0 = 2 * tid;
            float s0 = 0.f, s1 = 0.f;
            int cur = clss[0];
#pragma unroll 4
            for (int r = 0; r < MTILE; r++) {
                int c2 = clss[r];
                if (c2 != cur) {
                    atomicAdd(&Sl[(size_t)cur * DD + c0], s0);
                    atomicAdd(&Sl[(size_t)cur * DD + c0 + 1], s1);
                    s0 = 0.f; s1 = 0.f; cur = c2;
                }
                __half2 hv = *(__half2*)&Hh[r * 512 + c0];
                float2 f = __half22float2(hv);
                s0 += f.x; s1 += f.y;
            }
            atomicAdd(&Sl[(size_t)cur * DD + c0], s0);
            atomicAdd(&Sl[(size_t)cur * DD + c0 + 1], s1);
        }

        // reset accumulators for next level
#pragma unroll
        for (int i = 0; i < 4; i++)
#pragma unroll
            for (int j = 0; j < 8; j++)
#pragma unroll
                for (int q = 0; q < 4; q++) acc[i][j][q] = 0.f;
        // next level's top-of-loop sync orders H reads vs its ch1 load into stage 1
    }
}

// ---------------- finalize: 8 classes per CTA (grid 128) ----------------
#define FIN_SMEM_BYTES ((256 + 16384) * 4)

__global__ __launch_bounds__(512, 1)
void finalize_kernel(const float* __restrict__ W2, const float* __restrict__ b2,
                     const float* __restrict__ temps, float* __restrict__ out)
{
    extern __shared__ float smf[];
    float* As = smf;          // [8][32]
    float* Bs = smf + 256;    // [32][512]
    const int tid = threadIdx.x;
    const int row0 = blockIdx.x * 8;
    const int c_t = tid & 63, r_t = tid >> 6;   // r_t = class index 0..7

    float t0 = temps[0], t1 = temps[1], t2 = temps[2];
    float mx = fmaxf(t0, fmaxf(t1, t2));
    float e0 = expf(t0 - mx), e1 = expf(t1 - mx), e2 = expf(t2 - mx);
    float inv = 1.f / (e0 + e1 + e2);
    float w[3] = {e0 * inv, e1 * inv, e2 * inv};

    float acc[8];
#pragma unroll
    for (int j = 0; j < 8; j++) acc[j] = 0.f;

    const int c0 = c_t << 2;
    for (int l = 0; l < LL; l++) {
        for (int ch = 0; ch < 16; ch++) {
            __syncthreads();
            if (tid < 256) {
                int row = tid >> 5, kk = tid & 31;
                int cl = row0 + row;
                float cnt = fmaxf((float)g_counts[cl], 1.f);
                As[row * 32 + kk] =
                    g_S[(size_t)l * CC * DD + (size_t)cl * DD + ch * 32 + kk] * (w[l] / cnt);
            }
#pragma unroll
            for (int i = 0; i < 8; i++) {
                int idx = tid + i * 512;
                int k = idx >> 7, c4 = (idx & 127) << 2;
                *(float4*)(Bs + k * 512 + c4) =
                    *(const float4*)(W2 + (size_t)l * DD * DD + (size_t)(ch * 32 + k) * DD + c4);
            }
            __syncthreads();
#pragma unroll 4
            for (int k = 0; k < 32; k++) {
                float4 bA = *(const float4*)(Bs + k * 512 + c0);
                float4 bB = *(const float4*)(Bs + k * 512 + 256 + c0);
                float a = As[r_t * 32 + k];
                acc[0] += a * bA.x; acc[1] += a * bA.y;
                acc[2] += a * bA.z; acc[3] += a * bA.w;
                acc[4] += a * bB.x; acc[5] += a * bB.y;
                acc[6] += a * bB.z; acc[7] += a * bB.w;
            }
        }
    }

    {
        int cl = row0 + r_t;
        float has = (g_counts[cl] > 0) ? 1.f : 0.f;
        float4 v0, v1;
        v0.x = acc[0] + has * (w[0] * b2[c0]     + w[1] * b2[DD + c0]     + w[2] * b2[2 * DD + c0]);
        v0.y = acc[1] + has * (w[0] * b2[c0 + 1] + w[1] * b2[DD + c0 + 1] + w[2] * b2[2 * DD + c0 + 1]);
        v0.z = acc[2] + has * (w[0] * b2[c0 + 2] + w[1] * b2[DD + c0 + 2] + w[2] * b2[2 * DD + c0 + 2]);
        v0.w = acc[3] + has * (w[0] * b2[c0 + 3] + w[1] * b2[DD + c0 + 3] + w[2] * b2[2 * DD + c0 + 3]);
        int c1 = 256 + c0;
        v1.x = acc[4] + has * (w[0] * b2[c1]     + w[1] * b2[DD + c1]     + w[2] * b2[2 * DD + c1]);
        v1.y = acc[5] + has * (w[0] * b2[c1 + 1] + w[1] * b2[DD + c1 + 1] + w[2] * b2[2 * DD + c1 + 1]);
        v1.z = acc[6] + has * (w[0] * b2[c1 + 2] + w[1] * b2[DD + c1 + 2] + w[2] * b2[2 * DD + c1 + 2]);
        v1.w = acc[7] + has * (w[0] * b2[c1 + 3] + w[1] * b2[DD + c1 + 3] + w[2] * b2[2 * DD + c1 + 3]);
        *(float4*)(out + (size_t)cl * DD + c0) = v0;
        *(float4*)(out + (size_t)cl * DD + c1) = v1;
    }
}

// ---------------- launch ----------------
extern "C" void kernel_launch(void* const* d_in, const int* in_sizes, int n_in,
                              void* d_out, int out_size)
{
    const float* X      = (const float*)d_in[0];
    const int*   labels = (const int*)d_in[1];
    const float* W1     = (const float*)d_in[2];
    const float* b1     = (const float*)d_in[3];
    const float* gamma  = (const float*)d_in[4];
    const float* beta   = (const float*)d_in[5];
    const float* W2     = (const float*)d_in[6];
    const float* b2     = (const float*)d_in[7];
    const float* temps  = (const float*)d_in[8];
    float* out = (float*)d_out;

    cudaFuncSetAttribute(level_kernel, cudaFuncAttributeMaxDynamicSharedMemorySize,
                         LVL_SMEM_BYTES);
    cudaFuncSetAttribute(finalize_kernel, cudaFuncAttributeMaxDynamicSharedMemorySize,
                         FIN_SMEM_BYTES);

    zero_kernel<<<(LL * CC * DD + 255) / 256, 256>>>();
    hist_kernel<<<(NSUP + 255) / 256, 256>>>(labels);
    scan_kernel<<<1, CC>>>();
    perm_kernel<<<(NSUP + 255) / 256, 256>>>(labels);
    bprep_kernel<<<(LL * DD * DD + 255) / 256, 256>>>(W1);
    level_kernel<<<NSUP / MTILE, 256, LVL_SMEM_BYTES>>>(X, b1, gamma, beta);
    finalize_kernel<<<CC / 8, 512, FIN_SMEM_BYTES>>>(W2, b2, temps, out);
}

// round 14
// speedup vs baseline: 1.4974x; 1.0016x over previous
#include <cuda_runtime.h>
#include <cuda_fp16.h>
#include <cstdint>

#define NSUP 131072
#define DD   512
#define CC   1024
#define LL   3
#define MTILE 64
#define NCH  8          // K chunks of 64

// ---------------- device scratch ----------------
__device__ __half g_Bh[(size_t)LL * DD * DD];   // W1^T fp16: [l][n][k]
__device__ int   g_perm[NSUP];
__device__ int   g_cls[NSUP];
__device__ int   g_counts[CC];
__device__ int   g_cursor[CC];
__device__ int   g_off[CC];
__device__ float g_S[LL * CC * DD];

// ---------------- helpers ----------------
__device__ __forceinline__ uint32_t smem_u32(const void* p) {
    uint32_t a;
    asm("{ .reg .u64 t; cvta.to.shared.u64 t, %1; cvt.u32.u64 %0, t; }" : "=r"(a) : "l"(p));
    return a;
}
__device__ __forceinline__ uint32_t f2_to_h2(float lo, float hi) {
    uint32_t r;
    asm("cvt.rn.f16x2.f32 %0, %1, %2;" : "=r"(r) : "f"(hi), "f"(lo));
    return r;
}
__device__ __forceinline__ void cp_async16(void* sdst, const void* gsrc) {
    unsigned s = (unsigned)__cvta_generic_to_shared(sdst);
    asm volatile("cp.async.cg.shared.global [%0], [%1], 16;" :: "r"(s), "l"(gsrc));
}
__device__ __forceinline__ void cp_commit() { asm volatile("cp.async.commit_group;"); }
__device__ __forceinline__ void cp_wait0()  { asm volatile("cp.async.wait_group 0;"); }

__device__ __forceinline__ void ldsm4(uint32_t* r, uint32_t addr) {
    asm volatile("ldmatrix.sync.aligned.m8n8.x4.shared.b16 {%0,%1,%2,%3}, [%4];"
                 : "=r"(r[0]), "=r"(r[1]), "=r"(r[2]), "=r"(r[3]) : "r"(addr));
}
__device__ __forceinline__ void mma16816(float* c, const uint32_t* a, uint32_t b0, uint32_t b1) {
    asm volatile(
        "mma.sync.aligned.m16n8k16.row.col.f32.f16.f16.f32 "
        "{%0,%1,%2,%3}, {%4,%5,%6,%7}, {%8,%9}, {%0,%1,%2,%3};"
        : "+f"(c[0]), "+f"(c[1]), "+f"(c[2]), "+f"(c[3])
        : "r"(a[0]), "r"(a[1]), "r"(a[2]), "r"(a[3]), "r"(b0), "r"(b1));
}

// ---------------- prep: zero g_S/counts/cursor + W1 transpose->fp16, one launch ----
__global__ void prep_kernel(const float* __restrict__ W1) {
    int i = blockIdx.x * 256 + threadIdx.x;          // grid 3072*256 = 786432
    if (i < (LL * CC * DD) / 4)
        ((float4*)g_S)[i] = make_float4(0.f, 0.f, 0.f, 0.f);
    if (i < CC) { g_counts[i] = 0; g_cursor[i] = 0; }
    if (i < LL * DD * DD) {
        int l = i >> 18;
        int rem = i & ((1 << 18) - 1);
        int k = rem >> 9, n = rem & 511;
        g_Bh[((size_t)(l * DD + n) << 9) + k] = __float2half_rn(W1[i]);
    }
}

__global__ void hist_kernel(const int* __restrict__ labels) {
    int i = blockIdx.x * 256 + threadIdx.x;
    if (i < NSUP) atomicAdd(&g_counts[labels[i]], 1);
}
__global__ void scan_kernel() {
    __shared__ int tmp[CC];
    int t = threadIdx.x;
    int v = g_counts[t];
    tmp[t] = v;
    __syncthreads();
    for (int o = 1; o < CC; o <<= 1) {
        int add = (t >= o) ? tmp[t - o] : 0;
        __syncthreads();
        tmp[t] += add;
        __syncthreads();
    }
    g_off[t] = tmp[t] - v;
}
__global__ void perm_kernel(const int* __restrict__ labels) {
    int i = blockIdx.x * 256 + threadIdx.x;
    if (i >= NSUP) return;
    int c = labels[i];
    int pos = g_off[c] + atomicAdd(&g_cursor[c], 1);
    g_perm[pos] = i;
    g_cls[pos] = c;
}

// ---------------- fused level kernel: 1 CTA = 64 rows x all 3 levels (R11/R13 exact) ----
#define OFF_A   0
#define OFF_B   65536
#define OFF_B1  196608
#define OFF_G   198656
#define OFF_BT  200704
#define OFF_CL  202752
#define OFF_PM  203008
#define OFF_PS  203264
#define OFF_PQ  205312
#define OFF_MU  207360
#define OFF_RS  207616
#define LVL_SMEM_BYTES (207872 + 1024)

__device__ __forceinline__ void load_B(char* Bd, const __half* Bp, int ch, int tid) {
#pragma unroll
    for (int i = 0; i < 16; i++) {
        int o = tid + 256 * i;
        int n = o >> 3, b = (o & 7) * 16;
        uint32_t sw = (uint32_t)(n * 128) + (uint32_t)(b ^ ((n & 7) << 4));
        cp_async16(Bd + sw, (const char*)Bp + ((size_t)n * 1024 + ch * 128 + b));
    }
    cp_commit();
}

__global__ __launch_bounds__(256, 1)
void level_kernel(const float* __restrict__ X, const float* __restrict__ b1,
                  const float* __restrict__ gamma, const float* __restrict__ beta)
{
    extern __shared__ char raw[];
    char* sm = (char*)(((uintptr_t)raw + 1023) & ~(uintptr_t)1023);
    const int row0 = blockIdx.x * MTILE;
    const int tid = threadIdx.x;
    const int wid = tid >> 5, lane = tid & 31;   // 8 warps, warp tile 64 rows x 64 cols
    const uint32_t sbase = smem_u32(sm);

    float* b1s = (float*)(sm + OFF_B1);
    float* gms = (float*)(sm + OFF_G);
    float* bts = (float*)(sm + OFF_BT);
    int*   clss = (int*)(sm + OFF_CL);
    int*   sperm = (int*)(sm + OFF_PM);
    float* part_s = (float*)(sm + OFF_PS);   // [64][8]
    float* part_q = (float*)(sm + OFF_PQ);
    float* smu = (float*)(sm + OFF_MU);
    float* srs = (float*)(sm + OFF_RS);

    if (tid < MTILE) {
        clss[tid] = g_cls[row0 + tid];
        sperm[tid] = g_perm[row0 + tid];
    }
    __syncthreads();

    // start B level-0 chunk-0 immediately (overlaps A gather)
    load_B(sm + OFF_B, g_Bh, 0, tid);

    // A gather full-K once: f32 -> fp16, swizzled chunked layout
#pragma unroll
    for (int ch = 0; ch < NCH; ch++) {
#pragma unroll
        for (int i = 0; i < 2; i++) {
            int o = tid + 256 * i;
            int r = o >> 3, b = (o & 7) * 16;
            const float* src = X + (size_t)sperm[r] * DD + ch * 64 + (o & 7) * 8;
            float4 x0 = *(const float4*)(src);
            float4 x1 = *(const float4*)(src + 4);
            uint4 v;
            v.x = f2_to_h2(x0.x, x0.y);
            v.y = f2_to_h2(x0.z, x0.w);
            v.z = f2_to_h2(x1.x, x1.y);
            v.w = f2_to_h2(x1.z, x1.w);
            uint32_t sw = (uint32_t)(r * 128) + (uint32_t)(b ^ ((r & 7) << 4));
            *(uint4*)(sm + OFF_A + ch * 8192 + sw) = v;
        }
    }

    // fragment address components (validated R5/R6/R9/R11)
    uint32_t art[4], axr[4];
#pragma unroll
    for (int mf = 0; mf < 4; mf++) {
        int r = (lane & 15) + mf * 16;
        art[mf] = (uint32_t)(r * 128);
        axr[mf] = (uint32_t)((r & 7) << 4);
    }
    const uint32_t a_ts = (uint32_t)((lane >> 4) * 16);
    int bn = (lane & 7) + ((lane >> 4) & 1) * 8;
    const uint32_t b_kh = (uint32_t)(((lane >> 3) & 1) * 16);
    uint32_t brt[4], bxr[4];
#pragma unroll
    for (int nf2 = 0; nf2 < 4; nf2++) {
        int n = wid * 64 + nf2 * 16 + bn;
        brt[nf2] = (uint32_t)(n * 128);
        bxr[nf2] = (uint32_t)((n & 7) << 4);
    }

    float acc[4][8][4];
#pragma unroll
    for (int i = 0; i < 4; i++)
#pragma unroll
        for (int j = 0; j < 8; j++)
#pragma unroll
            for (int q = 0; q < 4; q++) acc[i][j][q] = 0.f;

    __half* Hh = (__half*)(sm + OFF_B + 65536);   // overlays B stage 1

    for (int l = 0; l < LL; l++) {
        for (int ch = 0; ch < NCH; ch++) {
            const int buf = ch & 1;
            cp_wait0();
            __syncthreads();   // buf ready + all threads past previous compute/epilogue

            // prefetch next chunk (possibly next level's ch0) into other stage
            int nl = l, nc = ch + 1;
            if (nc == NCH) { nl = l + 1; nc = 0; }
            if (nl < LL)
                load_B(sm + OFF_B + (buf ^ 1) * 65536,
                       g_Bh + (size_t)nl * DD * DD, nc, tid);

            const uint32_t Ab = sbase + OFF_A + ch * 8192;
            const uint32_t Bb = sbase + OFF_B + buf * 65536;
#pragma unroll
            for (int ks = 0; ks < 4; ks++) {
                const uint32_t koff = ks * 32;
                uint32_t a[4][4];
#pragma unroll
                for (int mf = 0; mf < 4; mf++)
                    ldsm4(a[mf], Ab + art[mf] + ((koff + a_ts) ^ axr[mf]));
#pragma unroll
                for (int nf2 = 0; nf2 < 4; nf2++) {
                    uint32_t bh[4];
                    ldsm4(bh, Bb + brt[nf2] + ((koff + b_kh) ^ bxr[nf2]));
#pragma unroll
                    for (int mf = 0; mf < 4; mf++) {
                        mma16816(acc[mf][nf2 * 2],     a[mf], bh[0], bh[1]);
                        mma16816(acc[mf][nf2 * 2 + 1], a[mf], bh[2], bh[3]);
                    }
                }
            }
        }

        // ================= epilogue for level l (H never stored pre-norm) ===========
        __syncthreads();   // everyone done with MMA reads of B stage 0 (H is on stage 1;
                           // next-level ch0 already prefetched into stage 0)
        b1s[tid] = b1[l * DD + tid];       b1s[tid + 256] = b1[l * DD + tid + 256];
        gms[tid] = gamma[l * DD + tid];    gms[tid + 256] = gamma[l * DD + tid + 256];
        bts[tid] = beta[l * DD + tid];     bts[tid + 256] = beta[l * DD + tid + 256];
        __syncthreads();

        // fold b1 into acc, per-thread partial sums per row-position
        float s8[4][2], q8[4][2];
#pragma unroll
        for (int mf = 0; mf < 4; mf++) { s8[mf][0] = s8[mf][1] = 0.f; q8[mf][0] = q8[mf][1] = 0.f; }
#pragma unroll
        for (int nf = 0; nf < 8; nf++) {
            const int colb = wid * 64 + (lane & 3) * 2 + nf * 8;
            const float bb0 = b1s[colb], bb1 = b1s[colb + 1];
#pragma unroll
            for (int mf = 0; mf < 4; mf++) {
#pragma unroll
                for (int hh = 0; hh < 2; hh++) {
                    float v0 = acc[mf][nf][2 * hh]     + bb0;
                    float v1 = acc[mf][nf][2 * hh + 1] + bb1;
                    acc[mf][nf][2 * hh]     = v0;
                    acc[mf][nf][2 * hh + 1] = v1;
                    s8[mf][hh] += v0 + v1;
                    q8[mf][hh] += v0 * v0 + v1 * v1;
                }
            }
        }
        // combine the 4 lanes sharing each row, store warp partials
#pragma unroll
        for (int mf = 0; mf < 4; mf++)
#pragma unroll
            for (int hh = 0; hh < 2; hh++) {
                float s = s8[mf][hh], q = q8[mf][hh];
                s += __shfl_xor_sync(0xffffffffu, s, 1);
                s += __shfl_xor_sync(0xffffffffu, s, 2);
                q += __shfl_xor_sync(0xffffffffu, q, 1);
                q += __shfl_xor_sync(0xffffffffu, q, 2);
                if ((lane & 3) == 0) {
                    int row = (lane >> 2) + 8 * hh + 16 * mf;
                    part_s[row * 8 + wid] = s;
                    part_q[row * 8 + wid] = q;
                }
            }
        __syncthreads();
        if (tid < MTILE) {
            float s = 0.f, q = 0.f;
#pragma unroll
            for (int w = 0; w < 8; w++) { s += part_s[tid * 8 + w]; q += part_q[tid * 8 + w]; }
            float mu = s * (1.f / 512.f);
            float var = q * (1.f / 512.f) - mu * mu;
            smu[tid] = mu;
            srs[tid] = rsqrtf(var + 1e-5f);
        }
        __syncthreads();

        // normalize + ReLU from registers -> fp16 H
#pragma unroll
        for (int nf = 0; nf < 8; nf++) {
            const int colb = wid * 64 + (lane & 3) * 2 + nf * 8;
            const float g0 = gms[colb], g1 = gms[colb + 1];
            const float t0 = bts[colb], t1 = bts[colb + 1];
#pragma unroll
            for (int mf = 0; mf < 4; mf++)
#pragma unroll
                for (int hh = 0; hh < 2; hh++) {
                    int row = (lane >> 2) + 8 * hh + 16 * mf;
                    float mu = smu[row], rs = srs[row];
                    float v0 = fmaxf((acc[mf][nf][2 * hh]     - mu) * rs * g0 + t0, 0.f);
                    float v1 = fmaxf((acc[mf][nf][2 * hh + 1] - mu) * rs * g1 + t1, 0.f);
                    *(uint32_t*)&Hh[row * 512 + colb] = f2_to_h2(v0, v1);
                }
        }
        __syncthreads();

        // class-segment reduce (2 cols/thread) + atomics
        {
            float* Sl = g_S + (size_t)l * CC * DD;
            const int c0 = 2 * tid;
            float s0 = 0.f, s1 = 0.f;
            int cur = clss[0];
#pragma unroll 4
            for (int r = 0; r < MTILE; r++) {
                int c2 = clss[r];
                if (c2 != cur) {
                    atomicAdd(&Sl[(size_t)cur * DD + c0], s0);
                    atomicAdd(&Sl[(size_t)cur * DD + c0 + 1], s1);
                    s0 = 0.f; s1 = 0.f; cur = c2;
                }
                __half2 hv = *(__half2*)&Hh[r * 512 + c0];
                float2 f = __half22float2(hv);
                s0 += f.x; s1 += f.y;
            }
            atomicAdd(&Sl[(size_t)cur * DD + c0], s0);
            atomicAdd(&Sl[(size_t)cur * DD + c0 + 1], s1);
        }

        // reset accumulators for next level
#pragma unroll
        for (int i = 0; i < 4; i++)
#pragma unroll
            for (int j = 0; j < 8; j++)
#pragma unroll
                for (int q = 0; q < 4; q++) acc[i][j][q] = 0.f;
    }
}

// ---------------- finalize: 8 classes per CTA (grid 128) ----------------
#define FIN_SMEM_BYTES ((256 + 16384) * 4)

__global__ __launch_bounds__(512, 1)
void finalize_kernel(const float* __restrict__ W2, const float* __restrict__ b2,
                     const float* __restrict__ temps, float* __restrict__ out)
{
    extern __shared__ float smf[];
    float* As = smf;          // [8][32]
    float* Bs = smf + 256;    // [32][512]
    const int tid = threadIdx.x;
    const int row0 = blockIdx.x * 8;
    const int c_t = tid & 63, r_t = tid >> 6;   // r_t = class index 0..7

    float t0 = temps[0], t1 = temps[1], t2 = temps[2];
    float mx = fmaxf(t0, fmaxf(t1, t2));
    float e0 = expf(t0 - mx), e1 = expf(t1 - mx), e2 = expf(t2 - mx);
    float inv = 1.f / (e0 + e1 + e2);
    float w[3] = {e0 * inv, e1 * inv, e2 * inv};

    float acc[8];
#pragma unroll
    for (int j = 0; j < 8; j++) acc[j] = 0.f;

    const int c0 = c_t << 2;
    for (int l = 0; l < LL; l++) {
        for (int ch = 0; ch < 16; ch++) {
            __syncthreads();
            if (tid < 256) {
                int row = tid >> 5, kk = tid & 31;
                int cl = row0 + row;
                float cnt = fmaxf((float)g_counts[cl], 1.f);
                As[row * 32 + kk] =
                    g_S[(size_t)l * CC * DD + (size_t)cl * DD + ch * 32 + kk] * (w[l] / cnt);
            }
#pragma unroll
            for (int i = 0; i < 8; i++) {
                int idx = tid + i * 512;
                int k = idx >> 7, c4 = (idx & 127) << 2;
                *(float4*)(Bs + k * 512 + c4) =
                    *(const float4*)(W2 + (size_t)l * DD * DD + (size_t)(ch * 32 + k) * DD + c4);
            }
            __syncthreads();
#pragma unroll 4
            for (int k = 0; k < 32; k++) {
                float4 bA = *(const float4*)(Bs + k * 512 + c0);
                float4 bB = *(const float4*)(Bs + k * 512 + 256 + c0);
                float a = As[r_t * 32 + k];
                acc[0] += a * bA.x; acc[1] += a * bA.y;
                acc[2] += a * bA.z; acc[3] += a * bA.w;
                acc[4] += a * bB.x; acc[5] += a * bB.y;
                acc[6] += a * bB.z; acc[7] += a * bB.w;
            }
        }
    }

    {
        int cl = row0 + r_t;
        float has = (g_counts[cl] > 0) ? 1.f : 0.f;
        float4 v0, v1;
        v0.x = acc[0] + has * (w[0] * b2[c0]     + w[1] * b2[DD + c0]     + w[2] * b2[2 * DD + c0]);
        v0.y = acc[1] + has * (w[0] * b2[c0 + 1] + w[1] * b2[DD + c0 + 1] + w[2] * b2[2 * DD + c0 + 1]);
        v0.z = acc[2] + has * (w[0] * b2[c0 + 2] + w[1] * b2[DD + c0 + 2] + w[2] * b2[2 * DD + c0 + 2]);
        v0.w = acc[3] + has * (w[0] * b2[c0 + 3] + w[1] * b2[DD + c0 + 3] + w[2] * b2[2 * DD + c0 + 3]);
        int c1 = 256 + c0;
        v1.x = acc[4] + has * (w[0] * b2[c1]     + w[1] * b2[DD + c1]     + w[2] * b2[2 * DD + c1]);
        v1.y = acc[5] + has * (w[0] * b2[c1 + 1] + w[1] * b2[DD + c1 + 1] + w[2] * b2[2 * DD + c1 + 1]);
        v1.z = acc[6] + has * (w[0] * b2[c1 + 2] + w[1] * b2[DD + c1 + 2] + w[2] * b2[2 * DD + c1 + 2]);
        v1.w = acc[7] + has * (w[0] * b2[c1 + 3] + w[1] * b2[DD + c1 + 3] + w[2] * b2[2 * DD + c1 + 3]);
        *(float4*)(out + (size_t)cl * DD + c0) = v0;
        *(float4*)(out + (size_t)cl * DD + c1) = v1;
    }
}

// ---------------- launch ----------------
extern "C" void kernel_launch(void* const* d_in, const int* in_sizes, int n_in,
                              void* d_out, int out_size)
{
    const float* X      = (const float*)d_in[0];
    const int*   labels = (const int*)d_in[1];
    const float* W1     = (const float*)d_in[2];
    const float* b1     = (const float*)d_in[3];
    const float* gamma  = (const float*)d_in[4];
    const float* beta   = (const float*)d_in[5];
    const float* W2     = (const float*)d_in[6];
    const float* b2     = (const float*)d_in[7];
    const float* temps  = (const float*)d_in[8];
    float* out = (float*)d_out;

    cudaFuncSetAttribute(level_kernel, cudaFuncAttributeMaxDynamicSharedMemorySize,
                         LVL_SMEM_BYTES);
    cudaFuncSetAttribute(finalize_kernel, cudaFuncAttributeMaxDynamicSharedMemorySize,
                         FIN_SMEM_BYTES);

    prep_kernel<<<(LL * DD * DD + 255) / 256, 256>>>(W1);     // zero g_S/counts + W1->fp16
    hist_kernel<<<(NSUP + 255) / 256, 256>>>(labels);
    scan_kernel<<<1, CC>>>();
    perm_kernel<<<(NSUP + 255) / 256, 256>>>(labels);
    level_kernel<<<NSUP / MTILE, 256, LVL_SMEM_BYTES>>>(X, b1, gamma, beta);
    finalize_kernel<<<CC / 8, 512, FIN_SMEM_BYTES>>>(W2, b2, temps, out);
}

// round 15
// speedup vs baseline: 1.4975x; 1.0001x over previous
#include <cuda_runtime.h>
#include <cuda_fp16.h>
#include <cstdint>

#define NSUP 131072
#define DD   512
#define CC   1024
#define LL   3
#define MTILE 64
#define NCH  8          // K chunks of 64

// ---------------- device scratch ----------------
__device__ __half g_Bh[(size_t)LL * DD * DD];   // W1^T fp16: [l][n][k]
__device__ int   g_perm[NSUP];
__device__ int   g_cls[NSUP];
__device__ int   g_counts[CC];
__device__ int   g_cursor[CC];
__device__ int   g_off[CC];
__device__ float g_S[LL * CC * DD];

// ---------------- helpers ----------------
__device__ __forceinline__ uint32_t smem_u32(const void* p) {
    uint32_t a;
    asm("{ .reg .u64 t; cvta.to.shared.u64 t, %1; cvt.u32.u64 %0, t; }" : "=r"(a) : "l"(p));
    return a;
}
__device__ __forceinline__ uint32_t f2_to_h2(float lo, float hi) {
    uint32_t r;
    asm("cvt.rn.f16x2.f32 %0, %1, %2;" : "=r"(r) : "f"(hi), "f"(lo));
    return r;
}
__device__ __forceinline__ void cp_async16(void* sdst, const void* gsrc) {
    unsigned s = (unsigned)__cvta_generic_to_shared(sdst);
    asm volatile("cp.async.cg.shared.global [%0], [%1], 16;" :: "r"(s), "l"(gsrc));
}
__device__ __forceinline__ void cp_commit() { asm volatile("cp.async.commit_group;"); }
__device__ __forceinline__ void cp_wait0()  { asm volatile("cp.async.wait_group 0;"); }

__device__ __forceinline__ void ldsm4(uint32_t* r, uint32_t addr) {
    asm volatile("ldmatrix.sync.aligned.m8n8.x4.shared.b16 {%0,%1,%2,%3}, [%4];"
                 : "=r"(r[0]), "=r"(r[1]), "=r"(r[2]), "=r"(r[3]) : "r"(addr));
}
__device__ __forceinline__ void mma16816(float* c, const uint32_t* a, uint32_t b0, uint32_t b1) {
    asm volatile(
        "mma.sync.aligned.m16n8k16.row.col.f32.f16.f16.f32 "
        "{%0,%1,%2,%3}, {%4,%5,%6,%7}, {%8,%9}, {%0,%1,%2,%3};"
        : "+f"(c[0]), "+f"(c[1]), "+f"(c[2]), "+f"(c[3])
        : "r"(a[0]), "r"(a[1]), "r"(a[2]), "r"(a[3]), "r"(b0), "r"(b1));
}

// ---------------- prep: zero g_S + W1 transpose->fp16, one launch ----------------
__global__ void prep_kernel(const float* __restrict__ W1) {
    int i = blockIdx.x * 256 + threadIdx.x;          // grid covers 786432
    if (i < (LL * CC * DD) / 4)
        ((float4*)g_S)[i] = make_float4(0.f, 0.f, 0.f, 0.f);
    if (i < LL * DD * DD) {
        int l = i >> 18;
        int rem = i & ((1 << 18) - 1);
        int k = rem >> 9, n = rem & 511;
        g_Bh[((size_t)(l * DD + n) << 9) + k] = __float2half_rn(W1[i]);
    }
}

// ---------------- fused hist + scan (single CTA, smem atomics) ----------------
__global__ __launch_bounds__(1024, 1)
void histscan_kernel(const int* __restrict__ labels) {
    __shared__ int hist[CC];
    int t = threadIdx.x;
    hist[t] = 0;
    __syncthreads();
    for (int i = t; i < NSUP; i += 1024)
        atomicAdd(&hist[labels[i]], 1);
    __syncthreads();
    int v = hist[t];
    // Hillis-Steele inclusive scan in smem
    __shared__ int tmp[CC];
    tmp[t] = v;
    __syncthreads();
    for (int o = 1; o < CC; o <<= 1) {
        int add = (t >= o) ? tmp[t - o] : 0;
        __syncthreads();
        tmp[t] += add;
        __syncthreads();
    }
    g_counts[t] = v;
    g_off[t] = tmp[t] - v;   // exclusive prefix
    g_cursor[t] = 0;
}

__global__ void perm_kernel(const int* __restrict__ labels) {
    int i = blockIdx.x * 256 + threadIdx.x;
    if (i >= NSUP) return;
    int c = labels[i];
    int pos = g_off[c] + atomicAdd(&g_cursor[c], 1);
    g_perm[pos] = i;
    g_cls[pos] = c;
}

// ---------------- fused level kernel: 1 CTA = 64 rows x all 3 levels (R11/R13 exact) ----
#define OFF_A   0
#define OFF_B   65536
#define OFF_B1  196608
#define OFF_G   198656
#define OFF_BT  200704
#define OFF_CL  202752
#define OFF_PM  203008
#define OFF_PS  203264
#define OFF_PQ  205312
#define OFF_MU  207360
#define OFF_RS  207616
#define LVL_SMEM_BYTES (207872 + 1024)

__device__ __forceinline__ void load_B(char* Bd, const __half* Bp, int ch, int tid) {
#pragma unroll
    for (int i = 0; i < 16; i++) {
        int o = tid + 256 * i;
        int n = o >> 3, b = (o & 7) * 16;
        uint32_t sw = (uint32_t)(n * 128) + (uint32_t)(b ^ ((n & 7) << 4));
        cp_async16(Bd + sw, (const char*)Bp + ((size_t)n * 1024 + ch * 128 + b));
    }
    cp_commit();
}

__global__ __launch_bounds__(256, 1)
void level_kernel(const float* __restrict__ X, const float* __restrict__ b1,
                  const float* __restrict__ gamma, const float* __restrict__ beta)
{
    extern __shared__ char raw[];
    char* sm = (char*)(((uintptr_t)raw + 1023) & ~(uintptr_t)1023);
    const int row0 = blockIdx.x * MTILE;
    const int tid = threadIdx.x;
    const int wid = tid >> 5, lane = tid & 31;   // 8 warps, warp tile 64 rows x 64 cols
    const uint32_t sbase = smem_u32(sm);

    float* b1s = (float*)(sm + OFF_B1);
    float* gms = (float*)(sm + OFF_G);
    float* bts = (float*)(sm + OFF_BT);
    int*   clss = (int*)(sm + OFF_CL);
    int*   sperm = (int*)(sm + OFF_PM);
    float* part_s = (float*)(sm + OFF_PS);   // [64][8]
    float* part_q = (float*)(sm + OFF_PQ);
    float* smu = (float*)(sm + OFF_MU);
    float* srs = (float*)(sm + OFF_RS);

    if (tid < MTILE) {
        clss[tid] = g_cls[row0 + tid];
        sperm[tid] = g_perm[row0 + tid];
    }
    __syncthreads();

    // start B level-0 chunk-0 immediately (overlaps A gather)
    load_B(sm + OFF_B, g_Bh, 0, tid);

    // A gather full-K once: f32 -> fp16, swizzled chunked layout
#pragma unroll
    for (int ch = 0; ch < NCH; ch++) {
#pragma unroll
        for (int i = 0; i < 2; i++) {
            int o = tid + 256 * i;
            int r = o >> 3, b = (o & 7) * 16;
            const float* src = X + (size_t)sperm[r] * DD + ch * 64 + (o & 7) * 8;
            float4 x0 = *(const float4*)(src);
            float4 x1 = *(const float4*)(src + 4);
            uint4 v;
            v.x = f2_to_h2(x0.x, x0.y);
            v.y = f2_to_h2(x0.z, x0.w);
            v.z = f2_to_h2(x1.x, x1.y);
            v.w = f2_to_h2(x1.z, x1.w);
            uint32_t sw = (uint32_t)(r * 128) + (uint32_t)(b ^ ((r & 7) << 4));
            *(uint4*)(sm + OFF_A + ch * 8192 + sw) = v;
        }
    }

    // fragment address components (validated R5/R6/R9/R11)
    uint32_t art[4], axr[4];
#pragma unroll
    for (int mf = 0; mf < 4; mf++) {
        int r = (lane & 15) + mf * 16;
        art[mf] = (uint32_t)(r * 128);
        axr[mf] = (uint32_t)((r & 7) << 4);
    }
    const uint32_t a_ts = (uint32_t)((lane >> 4) * 16);
    int bn = (lane & 7) + ((lane >> 4) & 1) * 8;
    const uint32_t b_kh = (uint32_t)(((lane >> 3) & 1) * 16);
    uint32_t brt[4], bxr[4];
#pragma unroll
    for (int nf2 = 0; nf2 < 4; nf2++) {
        int n = wid * 64 + nf2 * 16 + bn;
        brt[nf2] = (uint32_t)(n * 128);
        bxr[nf2] = (uint32_t)((n & 7) << 4);
    }

    float acc[4][8][4];
#pragma unroll
    for (int i = 0; i < 4; i++)
#pragma unroll
        for (int j = 0; j < 8; j++)
#pragma unroll
            for (int q = 0; q < 4; q++) acc[i][j][q] = 0.f;

    __half* Hh = (__half*)(sm + OFF_B + 65536);   // overlays B stage 1

    for (int l = 0; l < LL; l++) {
        for (int ch = 0; ch < NCH; ch++) {
            const int buf = ch & 1;
            cp_wait0();
            __syncthreads();   // buf ready + all threads past previous compute/epilogue

            // prefetch next chunk (possibly next level's ch0) into other stage
            int nl = l, nc = ch + 1;
            if (nc == NCH) { nl = l + 1; nc = 0; }
            if (nl < LL)
                load_B(sm + OFF_B + (buf ^ 1) * 65536,
                       g_Bh + (size_t)nl * DD * DD, nc, tid);

            const uint32_t Ab = sbase + OFF_A + ch * 8192;
            const uint32_t Bb = sbase + OFF_B + buf * 65536;
#pragma unroll
            for (int ks = 0; ks < 4; ks++) {
                const uint32_t koff = ks * 32;
                uint32_t a[4][4];
#pragma unroll
                for (int mf = 0; mf < 4; mf++)
                    ldsm4(a[mf], Ab + art[mf] + ((koff + a_ts) ^ axr[mf]));
#pragma unroll
                for (int nf2 = 0; nf2 < 4; nf2++) {
                    uint32_t bh[4];
                    ldsm4(bh, Bb + brt[nf2] + ((koff + b_kh) ^ bxr[nf2]));
#pragma unroll
                    for (int mf = 0; mf < 4; mf++) {
                        mma16816(acc[mf][nf2 * 2],     a[mf], bh[0], bh[1]);
                        mma16816(acc[mf][nf2 * 2 + 1], a[mf], bh[2], bh[3]);
                    }
                }
            }
        }

        // ================= epilogue for level l (H never stored pre-norm) ===========
        __syncthreads();   // everyone done with MMA reads of B stage 0 (H is on stage 1;
                           // next-level ch0 already prefetched into stage 0)
        b1s[tid] = b1[l * DD + tid];       b1s[tid + 256] = b1[l * DD + tid + 256];
        gms[tid] = gamma[l * DD + tid];    gms[tid + 256] = gamma[l * DD + tid + 256];
        bts[tid] = beta[l * DD + tid];     bts[tid + 256] = beta[l * DD + tid + 256];
        __syncthreads();

        // fold b1 into acc, per-thread partial sums per row-position
        float s8[4][2], q8[4][2];
#pragma unroll
        for (int mf = 0; mf < 4; mf++) { s8[mf][0] = s8[mf][1] = 0.f; q8[mf][0] = q8[mf][1] = 0.f; }
#pragma unroll
        for (int nf = 0; nf < 8; nf++) {
            const int colb = wid * 64 + (lane & 3) * 2 + nf * 8;
            const float bb0 = b1s[colb], bb1 = b1s[colb + 1];
#pragma unroll
            for (int mf = 0; mf < 4; mf++) {
#pragma unroll
                for (int hh = 0; hh < 2; hh++) {
                    float v0 = acc[mf][nf][2 * hh]     + bb0;
                    float v1 = acc[mf][nf][2 * hh + 1] + bb1;
                    acc[mf][nf][2 * hh]     = v0;
                    acc[mf][nf][2 * hh + 1] = v1;
                    s8[mf][hh] += v0 + v1;
                    q8[mf][hh] += v0 * v0 + v1 * v1;
                }
            }
        }
        // combine the 4 lanes sharing each row, store warp partials
#pragma unroll
        for (int mf = 0; mf < 4; mf++)
#pragma unroll
            for (int hh = 0; hh < 2; hh++) {
                float s = s8[mf][hh], q = q8[mf][hh];
                s += __shfl_xor_sync(0xffffffffu, s, 1);
                s += __shfl_xor_sync(0xffffffffu, s, 2);
                q += __shfl_xor_sync(0xffffffffu, q, 1);
                q += __shfl_xor_sync(0xffffffffu, q, 2);
                if ((lane & 3) == 0) {
                    int row = (lane >> 2) + 8 * hh + 16 * mf;
                    part_s[row * 8 + wid] = s;
                    part_q[row * 8 + wid] = q;
                }
            }
        __syncthreads();
        if (tid < MTILE) {
            float s = 0.f, q = 0.f;
#pragma unroll
            for (int w = 0; w < 8; w++) { s += part_s[tid * 8 + w]; q += part_q[tid * 8 + w]; }
            float mu = s * (1.f / 512.f);
            float var = q * (1.f / 512.f) - mu * mu;
            smu[tid] = mu;
            srs[tid] = rsqrtf(var + 1e-5f);
        }
        __syncthreads();

        // normalize + ReLU from registers -> fp16 H
#pragma unroll
        for (int nf = 0; nf < 8; nf++) {
            const int colb = wid * 64 + (lane & 3) * 2 + nf * 8;
            const float g0 = gms[colb], g1 = gms[colb + 1];
            const float t0 = bts[colb], t1 = bts[colb + 1];
#pragma unroll
            for (int mf = 0; mf < 4; mf++)
#pragma unroll
                for (int hh = 0; hh < 2; hh++) {
                    int row = (lane >> 2) + 8 * hh + 16 * mf;
                    float mu = smu[row], rs = srs[row];
                    float v0 = fmaxf((acc[mf][nf][2 * hh]     - mu) * rs * g0 + t0, 0.f);
                    float v1 = fmaxf((acc[mf][nf][2 * hh + 1] - mu) * rs * g1 + t1, 0.f);
                    *(uint32_t*)&Hh[row * 512 + colb] = f2_to_h2(v0, v1);
                }
        }
        __syncthreads();

        // class-segment reduce (2 cols/thread) + atomics
        {
            float* Sl = g_S + (size_t)l * CC * DD;
            const int c0 = 2 * tid;
            float s0 = 0.f, s1 = 0.f;
            int cur = clss[0];
#pragma unroll 4
            for (int r = 0; r < MTILE; r++) {
                int c2 = clss[r];
                if (c2 != cur) {
                    atomicAdd(&Sl[(size_t)cur * DD + c0], s0);
                    atomicAdd(&Sl[(size_t)cur * DD + c0 + 1], s1);
                    s0 = 0.f; s1 = 0.f; cur = c2;
                }
                __half2 hv = *(__half2*)&Hh[r * 512 + c0];
                float2 f = __half22float2(hv);
                s0 += f.x; s1 += f.y;
            }
            atomicAdd(&Sl[(size_t)cur * DD + c0], s0);
            atomicAdd(&Sl[(size_t)cur * DD + c0 + 1], s1);
        }

        // reset accumulators for next level
#pragma unroll
        for (int i = 0; i < 4; i++)
#pragma unroll
            for (int j = 0; j < 8; j++)
#pragma unroll
                for (int q = 0; q < 4; q++) acc[i][j][q] = 0.f;
    }
}

// ---------------- finalize: 8 classes per CTA (grid 128) ----------------
#define FIN_SMEM_BYTES ((256 + 16384) * 4)

__global__ __launch_bounds__(512, 1)
void finalize_kernel(const float* __restrict__ W2, const float* __restrict__ b2,
                     const float* __restrict__ temps, float* __restrict__ out)
{
    extern __shared__ float smf[];
    float* As = smf;          // [8][32]
    float* Bs = smf + 256;    // [32][512]
    const int tid = threadIdx.x;
    const int row0 = blockIdx.x * 8;
    const int c_t = tid & 63, r_t = tid >> 6;   // r_t = class index 0..7

    float t0 = temps[0], t1 = temps[1], t2 = temps[2];
    float mx = fmaxf(t0, fmaxf(t1, t2));
    float e0 = expf(t0 - mx), e1 = expf(t1 - mx), e2 = expf(t2 - mx);
    float inv = 1.f / (e0 + e1 + e2);
    float w[3] = {e0 * inv, e1 * inv, e2 * inv};

    float acc[8];
#pragma unroll
    for (int j = 0; j < 8; j++) acc[j] = 0.f;

    const int c0 = c_t << 2;
    for (int l = 0; l < LL; l++) {
        for (int ch = 0; ch < 16; ch++) {
            __syncthreads();
            if (tid < 256) {
                int row = tid >> 5, kk = tid & 31;
                int cl = row0 + row;
                float cnt = fmaxf((float)g_counts[cl], 1.f);
                As[row * 32 + kk] =
                    g_S[(size_t)l * CC * DD + (size_t)cl * DD + ch * 32 + kk] * (w[l] / cnt);
            }
#pragma unroll
            for (int i = 0; i < 8; i++) {
                int idx = tid + i * 512;
                int k = idx >> 7, c4 = (idx & 127) << 2;
                *(float4*)(Bs + k * 512 + c4) =
                    *(const float4*)(W2 + (size_t)l * DD * DD + (size_t)(ch * 32 + k) * DD + c4);
            }
            __syncthreads();
#pragma unroll 4
            for (int k = 0; k < 32; k++) {
                float4 bA = *(const float4*)(Bs + k * 512 + c0);
                float4 bB = *(const float4*)(Bs + k * 512 + 256 + c0);
                float a = As[r_t * 32 + k];
                acc[0] += a * bA.x; acc[1] += a * bA.y;
                acc[2] += a * bA.z; acc[3] += a * bA.w;
                acc[4] += a * bB.x; acc[5] += a * bB.y;
                acc[6] += a * bB.z; acc[7] += a * bB.w;
            }
        }
    }

    {
        int cl = row0 + r_t;
        float has = (g_counts[cl] > 0) ? 1.f : 0.f;
        float4 v0, v1;
        v0.x = acc[0] + has * (w[0] * b2[c0]     + w[1] * b2[DD + c0]     + w[2] * b2[2 * DD + c0]);
        v0.y = acc[1] + has * (w[0] * b2[c0 + 1] + w[1] * b2[DD + c0 + 1] + w[2] * b2[2 * DD + c0 + 1]);
        v0.z = acc[2] + has * (w[0] * b2[c0 + 2] + w[1] * b2[DD + c0 + 2] + w[2] * b2[2 * DD + c0 + 2]);
        v0.w = acc[3] + has * (w[0] * b2[c0 + 3] + w[1] * b2[DD + c0 + 3] + w[2] * b2[2 * DD + c0 + 3]);
        int c1 = 256 + c0;
        v1.x = acc[4] + has * (w[0] * b2[c1]     + w[1] * b2[DD + c1]     + w[2] * b2[2 * DD + c1]);
        v1.y = acc[5] + has * (w[0] * b2[c1 + 1] + w[1] * b2[DD + c1 + 1] + w[2] * b2[2 * DD + c1 + 1]);
        v1.z = acc[6] + has * (w[0] * b2[c1 + 2] + w[1] * b2[DD + c1 + 2] + w[2] * b2[2 * DD + c1 + 2]);
        v1.w = acc[7] + has * (w[0] * b2[c1 + 3] + w[1] * b2[DD + c1 + 3] + w[2] * b2[2 * DD + c1 + 3]);
        *(float4*)(out + (size_t)cl * DD + c0) = v0;
        *(float4*)(out + (size_t)cl * DD + c1) = v1;
    }
}

// ---------------- launch ----------------
extern "C" void kernel_launch(void* const* d_in, const int* in_sizes, int n_in,
                              void* d_out, int out_size)
{
    const float* X      = (const float*)d_in[0];
    const int*   labels = (const int*)d_in[1];
    const float* W1     = (const float*)d_in[2];
    const float* b1     = (const float*)d_in[3];
    const float* gamma  = (const float*)d_in[4];
    const float* beta   = (const float*)d_in[5];
    const float* W2     = (const float*)d_in[6];
    const float* b2     = (const float*)d_in[7];
    const float* temps  = (const float*)d_in[8];
    float* out = (float*)d_out;

    cudaFuncSetAttribute(level_kernel, cudaFuncAttributeMaxDynamicSharedMemorySize,
                         LVL_SMEM_BYTES);
    cudaFuncSetAttribute(finalize_kernel, cudaFuncAttributeMaxDynamicSharedMemorySize,
                         FIN_SMEM_BYTES);

    histscan_kernel<<<1, 1024>>>(labels);                     // hist + scan + cursor=0
    prep_kernel<<<(LL * DD * DD + 255) / 256, 256>>>(W1);     // zero g_S + W1->fp16
    perm_kernel<<<(NSUP + 255) / 256, 256>>>(labels);
    level_kernel<<<NSUP / MTILE, 256, LVL_SMEM_BYTES>>>(X, b1, gamma, beta);
    finalize_kernel<<<CC / 8, 512, FIN_SMEM_BYTES>>>(W2, b2, temps, out);
}